// round 13
// baseline (speedup 1.0000x reference)
#include <cuda_runtime.h>
#include <cuda_fp16.h>
#include <cstdint>

// Problem constants
#define BATCHN 2
#define SEQL   2048
#define DIMN   2048
#define NH     16
#define NKV    8
#define HD     128
#define NCH    16
#define CHK    128
#define KP     2048
#define BKC    32
#define STR    40
#define NITG   (KP / BKC)   // 64

#define QSCALE   4096.0f
#define QDESCALE (1.0f / 4096.0f)

// ---------------------------------------------------------------------------
// Scratch
// ---------------------------------------------------------------------------
__device__ float g_colsum[BATCHN * NKV * HD];

__device__ unsigned short g_x2[(size_t)4096 * KP];
__device__ unsigned short g_w2[(size_t)4096 * KP];
__device__ unsigned short g_a2[(size_t)4096 * KP];
__device__ unsigned short g_wo2[(size_t)2048 * KP];

__device__ __half g_qh0[(size_t)BATCHN * NH * SEQL * HD];   // raw q (pre-rope) fp16
__device__ __half g_kh[(size_t)BATCHN * NKV * SEQL * HD];   // raw k (pre-rope) fp16
__device__ __half g_qh[(size_t)BATCHN * NH * SEQL * HD];    // q' * QSCALE
__device__ __half g_ekh[(size_t)BATCHN * NKV * SEQL * HD];  // exp(rope(k))
__device__ __half g_vh[(size_t)BATCHN * NKV * SEQL * HD];   // v
__device__ __half g_cumh[(size_t)BATCHN * NKV * NCH * HD * HD];

// ---------------------------------------------------------------------------
// PTX helpers
// ---------------------------------------------------------------------------
__device__ __forceinline__ uint32_t smem_u32(const void* p) {
    uint32_t a;
    asm("{ .reg .u64 t; cvta.to.shared.u64 t, %1; cvt.u32.u64 %0, t; }"
        : "=r"(a) : "l"(p));
    return a;
}
__device__ __forceinline__ void ldm_x4(uint32_t* r, uint32_t addr) {
    asm volatile("ldmatrix.sync.aligned.m8n8.x4.shared.b16 {%0,%1,%2,%3}, [%4];"
                 : "=r"(r[0]), "=r"(r[1]), "=r"(r[2]), "=r"(r[3]) : "r"(addr));
}
__device__ __forceinline__ void ldm_x4_t(uint32_t* r, uint32_t addr) {
    asm volatile("ldmatrix.sync.aligned.m8n8.x4.trans.shared.b16 {%0,%1,%2,%3}, [%4];"
                 : "=r"(r[0]), "=r"(r[1]), "=r"(r[2]), "=r"(r[3]) : "r"(addr));
}
__device__ __forceinline__ void mma_16816(float* c, const uint32_t* a,
                                          uint32_t b0, uint32_t b1) {
    asm volatile(
        "mma.sync.aligned.m16n8k16.row.col.f32.f16.f16.f32 "
        "{%0,%1,%2,%3}, {%4,%5,%6,%7}, {%8,%9}, {%0,%1,%2,%3};"
        : "+f"(c[0]), "+f"(c[1]), "+f"(c[2]), "+f"(c[3])
        : "r"(a[0]), "r"(a[1]), "r"(a[2]), "r"(a[3]), "r"(b0), "r"(b1));
}
__device__ __forceinline__ void cp16(uint32_t s, const void* g) {
    asm volatile("cp.async.cg.shared.global [%0], [%1], 16;" :: "r"(s), "l"(g));
}
__device__ __forceinline__ void cp_commit() {
    asm volatile("cp.async.commit_group;" ::: "memory");
}
template <int N> __device__ __forceinline__ void cp_wait() {
    asm volatile("cp.async.wait_group %0;" :: "n"(N) : "memory");
}

// ---------------------------------------------------------------------------
// Fused fp32 -> fp16 conversion for all inputs.
// ---------------------------------------------------------------------------
__global__ __launch_bounds__(256) void k_cvt_all(
    const float* __restrict__ x,  const float* __restrict__ wq,
    const float* __restrict__ wk, const float* __restrict__ wv,
    const float* __restrict__ wo)
{
    int blk = blockIdx.x;
    const float* src;
    unsigned short* dst;
    size_t base;
    if (blk < 4096)      { src = x;  dst = g_x2;  base = (size_t)blk * 2048; }
    else if (blk < 6144) { src = wq; dst = g_w2;  base = (size_t)(blk - 4096) * 2048; }
    else if (blk < 7168) { src = wk; dst = g_w2 + (size_t)2048 * KP; base = (size_t)(blk - 6144) * 2048; }
    else if (blk < 8192) { src = wv; dst = g_w2 + (size_t)3072 * KP; base = (size_t)(blk - 7168) * 2048; }
    else                 { src = wo; dst = g_wo2; base = (size_t)(blk - 8192) * 2048; }

    size_t i = base + (size_t)threadIdx.x * 8;
    float4 v0 = *(const float4*)(src + i);
    float4 v1 = *(const float4*)(src + i + 4);
    float f[8] = {v0.x, v0.y, v0.z, v0.w, v1.x, v1.y, v1.z, v1.w};
    __align__(16) __half o[8];
#pragma unroll
    for (int j = 0; j < 8; j++) o[j] = __float2half(f[j]);
    *(uint4*)(dst + i) = *(const uint4*)o;
}

// ---------------------------------------------------------------------------
// HMMA fp16 GEMM. 128x128 tile, 4 warps (2x2), BK=32, 3-stage, 3 CTAs/SM.
// mode 0: scatter q/k/v fp16.  mode 1: row-major fp32 C.
// ---------------------------------------------------------------------------
#define A_BUF (128 * STR)
#define B_BUF (128 * STR)
#define GEMM_SMEM ((3 * (A_BUF + B_BUF)) * 2)   // 61440 bytes

__global__ __launch_bounds__(128, 3) void k_gemm_mma(
    const __half* __restrict__ A, const __half* __restrict__ B,
    float* __restrict__ C, int mode)
{
    extern __shared__ char smraw[];
    __half* sA = (__half*)smraw;
    __half* sB = sA + 3 * A_BUF;

    const int t = threadIdx.x, lane = t & 31, wid = t >> 5;
    const int wm = wid >> 1, wn = wid & 1;
    const int m0 = blockIdx.y * 128, n0 = blockIdx.x * 128;

    uint32_t sAb = smem_u32(sA);
    uint32_t sBb = smem_u32(sB);

    const __half* ga = A + (size_t)(m0 + (t >> 2)) * KP + (t & 3) * 8;
    const __half* gb = B + (size_t)(n0 + (t >> 2)) * KP + (t & 3) * 8;
    const uint32_t so = ((uint32_t)(t >> 2) * STR + (t & 3) * 8) * 2;

    auto load_tile = [&](int buf, int i) {
        uint32_t sa = sAb + (uint32_t)buf * A_BUF * 2 + so;
        uint32_t sb = sBb + (uint32_t)buf * B_BUF * 2 + so;
        int ko = i * BKC;
#pragma unroll
        for (int j = 0; j < 4; j++)
            cp16(sa + j * 32 * STR * 2, ga + (size_t)j * 32 * KP + ko);
#pragma unroll
        for (int j = 0; j < 4; j++)
            cp16(sb + j * 32 * STR * 2, gb + (size_t)j * 32 * KP + ko);
        cp_commit();
    };

    float acc[4][8][4];
#pragma unroll
    for (int i = 0; i < 4; i++)
#pragma unroll
        for (int j = 0; j < 8; j++)
#pragma unroll
            for (int r = 0; r < 4; r++) acc[i][j][r] = 0.f;

    const int lr = lane & 7;
    const int lm = (lane >> 3) & 1;
    const int lc = lane >> 4;

    load_tile(0, 0);
    load_tile(1, 1);

    for (int i = 0; i < NITG; i++) {
        if (i == NITG - 1) cp_wait<0>(); else cp_wait<1>();
        __syncthreads();

        int buf = i % 3;
        uint32_t sa = sAb + (uint32_t)buf * A_BUF * 2;
        uint32_t sb = sBb + (uint32_t)buf * B_BUF * 2;
#pragma unroll
        for (int ks = 0; ks < 2; ks++) {
            uint32_t afr[4][4], bfr[4][4];
            const uint32_t coff = ((uint32_t)(ks * 16 + lc * 8)) * 2;
#pragma unroll
            for (int mt = 0; mt < 4; mt++)
                ldm_x4(afr[mt],
                       sa + ((uint32_t)(wm * 64 + mt * 16 + lr + lm * 8) * STR) * 2 + coff);
#pragma unroll
            for (int nt2 = 0; nt2 < 4; nt2++)
                ldm_x4(bfr[nt2],
                       sb + ((uint32_t)(wn * 64 + nt2 * 16 + lr + lm * 8) * STR) * 2 + coff);
#pragma unroll
            for (int mt = 0; mt < 4; mt++)
#pragma unroll
                for (int nt = 0; nt < 8; nt++)
                    mma_16816(acc[mt][nt], afr[mt],
                              bfr[nt >> 1][nt & 1], bfr[nt >> 1][(nt & 1) + 2]);
        }

        if (i + 2 < NITG) load_tile((i + 2) % 3, i + 2);
    }

    // epilogue
    const int g = lane >> 2, c2 = (lane & 3) * 2;
#pragma unroll
    for (int mt = 0; mt < 4; mt++) {
#pragma unroll
        for (int half = 0; half < 2; half++) {
            int m = m0 + wm * 64 + mt * 16 + g + half * 8;
            if (mode == 0) {
                int b = m >> 11, s = m & 2047;
                int ht = n0 >> 7;
                __half* dsth;
                if (ht < 16)
                    dsth = g_qh0 + (((size_t)(b * NH + ht)) * SEQL + s) * HD;
                else if (ht < 24)
                    dsth = g_kh + (((size_t)(b * NKV + (ht - 16))) * SEQL + s) * HD;
                else
                    dsth = g_vh + (((size_t)(b * NKV + (ht - 24))) * SEQL + s) * HD;
#pragma unroll
                for (int nt = 0; nt < 8; nt++) {
                    int col = wn * 64 + nt * 8 + c2;
                    __half2 h2 = __floats2half2_rn(acc[mt][nt][half * 2],
                                                   acc[mt][nt][half * 2 + 1]);
                    *(__half2*)(dsth + col) = h2;
                }
            } else {
                float* dst = C + (size_t)m * DIMN + n0;
#pragma unroll
                for (int nt = 0; nt < 8; nt++) {
                    int col = wn * 64 + nt * 8 + c2;
                    float2 v2 = make_float2(acc[mt][nt][half * 2],
                                            acc[mt][nt][half * 2 + 1]);
                    *(float2*)(dst + col) = v2;
                }
            }
        }
    }
}

// ---------------------------------------------------------------------------
// K3: ekh = exp(rope(kh)) fp16 via __expf; accumulate column sums (fp32).
// ---------------------------------------------------------------------------
__global__ __launch_bounds__(256) void k_rope_k(const float* __restrict__ fc)
{
    __shared__ float s_part[8][128];
    int bhk = blockIdx.x;
    int w   = threadIdx.x >> 5;
    int l   = threadIdx.x & 31;
    float sum0 = 0.f, sum1 = 0.f, sum2 = 0.f, sum3 = 0.f;
#pragma unroll
    for (int r = 0; r < 8; r++) {
        int s = blockIdx.y * 64 + w * 8 + r;
        size_t off = ((size_t)bhk * SEQL + s) * HD + l * 4;
        __half2 a0 = *(const __half2*)(g_kh + off);
        __half2 a1 = *(const __half2*)(g_kh + off + 2);
        float vx = __low2float(a0), vy = __high2float(a0);
        float vz = __low2float(a1), vw = __high2float(a1);
        float4 f = *(const float4*)(fc + (size_t)s * HD + l * 4);
        float o0 = vx * f.x - vy * f.y;
        float o1 = vx * f.y + vy * f.x;
        float o2 = vz * f.z - vw * f.w;
        float o3 = vz * f.w + vw * f.z;
        float e0 = __expf(o0), e1 = __expf(o1), e2 = __expf(o2), e3 = __expf(o3);
        *(__half2*)(g_ekh + off)     = __floats2half2_rn(e0, e1);
        *(__half2*)(g_ekh + off + 2) = __floats2half2_rn(e2, e3);
        sum0 += e0; sum1 += e1; sum2 += e2; sum3 += e3;
    }
    s_part[w][l * 4 + 0] = sum0;
    s_part[w][l * 4 + 1] = sum1;
    s_part[w][l * 4 + 2] = sum2;
    s_part[w][l * 4 + 3] = sum3;
    __syncthreads();
    if (threadIdx.x < 128) {
        float a = 0.f;
#pragma unroll
        for (int w2 = 0; w2 < 8; w2++) a += s_part[w2][threadIdx.x];
        atomicAdd(&g_colsum[bhk * HD + threadIdx.x], a);
    }
}

// ---------------------------------------------------------------------------
// K4+K5 fused: per-bhk running kv prefix on HMMA, writing cum_excl directly.
// Block = (bhk, e-quarter of 32). acc registers ARE the prefix accumulator:
//   for each chunk n: write acc -> cumh[n] (fp16), then mma-accumulate chunk n.
// Double-buffered cp.async chunk prefetch. Also inverts g_colsum (fused rcp).
// ---------------------------------------------------------------------------
#define EKSTR 136
#define VSTR2 40
#define EKBUF (128 * EKSTR)     // halves per ek stage
#define VBUF2 (128 * VSTR2)
#define KVC_SMEM ((2 * (EKBUF + VBUF2)) * 2)   // 90112 bytes

__global__ __launch_bounds__(128, 1) void k_kvcum()
{
    extern __shared__ __half smc[];
    __half* ek0 = smc;                  // 2 stages of ek [m][d]
    __half* vv0 = smc + 2 * EKBUF;      // 2 stages of v  [m][32]

    const int bhk = blockIdx.x >> 2;    // 0..15
    const int eq  = blockIdx.x & 3;     // e-quarter
    const int t = threadIdx.x, lane = t & 31, w = t >> 5;

    // fused reciprocal of colsum (64 blocks x 32 = 2048)
    if (t < 32) {
        int i = blockIdx.x * 32 + t;
        g_colsum[i] = __frcp_rn(g_colsum[i]);
    }

    uint32_t ekb = smem_u32(ek0), vvb = smem_u32(vv0);

    auto load_chunk = [&](int buf, int n) {
        const __half* eb = g_ekh + ((size_t)bhk * SEQL + n * CHK) * HD;
        const __half* vb = g_vh  + ((size_t)bhk * SEQL + n * CHK) * HD + eq * 32;
        uint32_t ea = ekb + (uint32_t)buf * EKBUF * 2;
        uint32_t va = vvb + (uint32_t)buf * VBUF2 * 2;
#pragma unroll
        for (int it = 0; it < 16; it++) {
            int idx = it * 128 + t;
            int r = idx >> 4, seg = idx & 15;
            cp16(ea + ((uint32_t)r * EKSTR + seg * 8) * 2, eb + (size_t)r * HD + seg * 8);
        }
#pragma unroll
        for (int it = 0; it < 4; it++) {
            int idx = it * 128 + t;
            int r = idx >> 2, seg = idx & 3;
            cp16(va + ((uint32_t)r * VSTR2 + seg * 8) * 2, vb + (size_t)r * HD + seg * 8);
        }
        cp_commit();
    };

    const int lr = lane & 7, lm = (lane >> 3) & 1, lc = lane >> 4;
    const int g = lane >> 2, qd = (lane & 3) * 2;

    float acc[2][4][4];   // [d-tile][e-tile][frag] — running prefix
#pragma unroll
    for (int i = 0; i < 2; i++)
#pragma unroll
        for (int j = 0; j < 4; j++)
#pragma unroll
            for (int r = 0; r < 4; r++) acc[i][j][r] = 0.f;

    load_chunk(0, 0);

    for (int n = 0; n < NCH; n++) {
        // write cum_excl[n] from current acc (before accumulating chunk n)
        __half* ch = g_cumh + ((size_t)bhk * NCH + n) * (HD * HD) + eq * 32;
#pragma unroll
        for (int mt = 0; mt < 2; mt++)
#pragma unroll
            for (int half = 0; half < 2; half++) {
                int d = w * 32 + mt * 16 + g + half * 8;
#pragma unroll
                for (int nt = 0; nt < 4; nt++) {
                    __half2 h2 = __floats2half2_rn(acc[mt][nt][half * 2],
                                                   acc[mt][nt][half * 2 + 1]);
                    *(__half2*)(ch + (size_t)d * HD + nt * 8 + qd) = h2;
                }
            }

        if (n + 1 < NCH) { load_chunk((n + 1) & 1, n + 1); cp_wait<1>(); }
        else             { cp_wait<0>(); }
        __syncthreads();

        int buf = n & 1;
        uint32_t ea = ekb + (uint32_t)buf * EKBUF * 2;
        uint32_t va = vvb + (uint32_t)buf * VBUF2 * 2;
#pragma unroll
        for (int ks = 0; ks < 8; ks++) {
            uint32_t afr[2][4], tmp[4], bfr[2][4];
            const uint32_t rowA = ((uint32_t)(ks * 16 + lr + lm * 8)) * EKSTR;
#pragma unroll
            for (int mt = 0; mt < 2; mt++) {
                ldm_x4_t(tmp, ea + (rowA + w * 32 + mt * 16 + lc * 8) * 2);
                afr[mt][0] = tmp[0]; afr[mt][1] = tmp[2];
                afr[mt][2] = tmp[1]; afr[mt][3] = tmp[3];
            }
            const uint32_t rowV = ((uint32_t)(ks * 16 + lr + lm * 8)) * VSTR2;
#pragma unroll
            for (int ep = 0; ep < 2; ep++)
                ldm_x4_t(bfr[ep], va + (rowV + ep * 16 + lc * 8) * 2);
#pragma unroll
            for (int mt = 0; mt < 2; mt++)
#pragma unroll
                for (int nt = 0; nt < 4; nt++)
                    mma_16816(acc[mt][nt], afr[mt],
                              bfr[nt >> 1][(nt & 1) * 2], bfr[nt >> 1][(nt & 1) * 2 + 1]);
        }
        __syncthreads();   // protect buffer reuse by next iteration's load
    }
}

// ---------------------------------------------------------------------------
// K2: q' = softmax(rope(qh0)*s) * invcolsum * QSCALE -> fp16 (fast math).
// Runs AFTER k_kvcum (which inverts colsum).
// ---------------------------------------------------------------------------
__global__ __launch_bounds__(256) void k_rope_q(const float* __restrict__ fc)
{
    int r = blockIdx.x * 8 + (threadIdx.x >> 5);
    int l = threadIdx.x & 31;
    int s  = r & 2047;
    int bh = r >> 11;
    int h  = bh & 15;
    int b  = bh >> 4;

    size_t off = (size_t)r * HD + l * 4;
    __half2 a0 = *(const __half2*)(g_qh0 + off);
    __half2 a1 = *(const __half2*)(g_qh0 + off + 2);
    float vx = __low2float(a0), vy = __high2float(a0);
    float vz = __low2float(a1), vw = __high2float(a1);
    float4 f = *(const float4*)(fc + (size_t)s * HD + l * 4);
    const float scale = 0.08838834764831845f;
    float o0 = (vx * f.x - vy * f.y) * scale;
    float o1 = (vx * f.y + vy * f.x) * scale;
    float o2 = (vz * f.z - vw * f.w) * scale;
    float o3 = (vz * f.w + vw * f.z) * scale;

    float mx = fmaxf(fmaxf(o0, o1), fmaxf(o2, o3));
#pragma unroll
    for (int off2 = 16; off2; off2 >>= 1) mx = fmaxf(mx, __shfl_xor_sync(0xffffffffu, mx, off2));
    float e0 = __expf(o0 - mx), e1 = __expf(o1 - mx);
    float e2 = __expf(o2 - mx), e3 = __expf(o3 - mx);
    float ss = e0 + e1 + e2 + e3;
#pragma unroll
    for (int off2 = 16; off2; off2 >>= 1) ss += __shfl_xor_sync(0xffffffffu, ss, off2);
    float inv = __fdividef(QSCALE, ss);

    const float* csp = g_colsum + ((b * NKV + (h >> 1)) * HD) + l * 4;   // 1/colsum
    float4 cs = *(const float4*)csp;
    __half* qp = g_qh + off;
    *(__half2*)(qp)     = __floats2half2_rn(e0 * inv * cs.x, e1 * inv * cs.y);
    *(__half2*)(qp + 2) = __floats2half2_rn(e2 * inv * cs.z, e3 * inv * cs.w);
}

// ---------------------------------------------------------------------------
// K6: per-(b,h,chunk) attention on HMMA.
// ---------------------------------------------------------------------------
#define ASTR 136
#define ATILE (128 * ASTR)
#define ATTN2_SMEM (3 * ATILE * 2)   // 104448 bytes

__global__ __launch_bounds__(128, 2) void k_attn_tc()
{
    extern __shared__ __half smh[];
    __half* qs = smh;
    __half* es = smh + ATILE;
    __half* vs = smh + 2 * ATILE;

    const int bid = blockIdx.x;
    const int b = bid >> 8;
    const int h = (bid >> 4) & 15;
    const int n = bid & 15;
    const int hk = h >> 1;
    const int t = threadIdx.x, lane = t & 31, w = t >> 5;

    const __half* qb = g_qh  + (((size_t)(b * NH  + h ) * SEQL) + n * CHK) * HD;
    const __half* eb = g_ekh + (((size_t)(b * NKV + hk) * SEQL) + n * CHK) * HD;
    const __half* vb = g_vh  + (((size_t)(b * NKV + hk) * SEQL) + n * CHK) * HD;
    const __half* cb = g_cumh + ((size_t)(b * NKV + hk) * NCH + n) * (HD * HD);

    uint32_t qsb = smem_u32(qs), esb = smem_u32(es), vsb = smem_u32(vs);

#pragma unroll
    for (int it = 0; it < 16; it++) {
        int idx = it * 128 + t;
        int r = idx >> 4, seg = idx & 15;
        uint32_t so = ((uint32_t)r * ASTR + seg * 8) * 2;
        cp16(qsb + so, qb + (size_t)r * HD + seg * 8);
        cp16(esb + so, eb + (size_t)r * HD + seg * 8);
        cp16(vsb + so, vb + (size_t)r * HD + seg * 8);
    }
    cp_commit();
    cp_wait<0>();
    __syncthreads();

    const int lr = lane & 7, lm = (lane >> 3) & 1, lc = lane >> 4;
    const int g = lane >> 2, qd = (lane & 3) * 2;

    float sacc[2][16][4];
#pragma unroll
    for (int i = 0; i < 2; i++)
#pragma unroll
        for (int j = 0; j < 16; j++)
#pragma unroll
            for (int r = 0; r < 4; r++) sacc[i][j][r] = 0.f;

#pragma unroll
    for (int ks = 0; ks < 8; ks++) {
        uint32_t afr[2][4], bfr[8][4];
        const uint32_t coff = ((uint32_t)(ks * 16 + lc * 8)) * 2;
#pragma unroll
        for (int mt = 0; mt < 2; mt++)
            ldm_x4(afr[mt], qsb + ((uint32_t)(w * 32 + mt * 16 + lr + lm * 8) * ASTR) * 2 + coff);
#pragma unroll
        for (int p = 0; p < 8; p++)
            ldm_x4(bfr[p], esb + ((uint32_t)(p * 16 + lr + lm * 8) * ASTR) * 2 + coff);
#pragma unroll
        for (int mt = 0; mt < 2; mt++)
#pragma unroll
            for (int nt = 0; nt < 16; nt++)
                mma_16816(sacc[mt][nt], afr[mt],
                          bfr[nt >> 1][nt & 1], bfr[nt >> 1][(nt & 1) + 2]);
    }

    __syncthreads();
#pragma unroll
    for (int it = 0; it < 16; it++) {
        int idx = it * 128 + t;
        int r = idx >> 4, seg = idx & 15;
        cp16(esb + ((uint32_t)r * ASTR + seg * 8) * 2, cb + (size_t)r * HD + seg * 8);
    }
    cp_commit();

    uint32_t sfr[2][8][4];
#pragma unroll
    for (int mt = 0; mt < 2; mt++) {
        int c0 = w * 32 + mt * 16 + g;
#pragma unroll
        for (int j = 0; j < 8; j++) {
            int mA = j * 16 + qd;
            int mB = j * 16 + 8 + qd;
            float* e0 = sacc[mt][2 * j];
            float* e1 = sacc[mt][2 * j + 1];
            __half2 p0 = __floats2half2_rn(mA     <= c0     ? e0[0] : 0.f,
                                           mA + 1 <= c0     ? e0[1] : 0.f);
            __half2 p1 = __floats2half2_rn(mA     <= c0 + 8 ? e0[2] : 0.f,
                                           mA + 1 <= c0 + 8 ? e0[3] : 0.f);
            __half2 p2 = __floats2half2_rn(mB     <= c0     ? e1[0] : 0.f,
                                           mB + 1 <= c0     ? e1[1] : 0.f);
            __half2 p3 = __floats2half2_rn(mB     <= c0 + 8 ? e1[2] : 0.f,
                                           mB + 1 <= c0 + 8 ? e1[3] : 0.f);
            sfr[mt][j][0] = *(uint32_t*)&p0;
            sfr[mt][j][1] = *(uint32_t*)&p1;
            sfr[mt][j][2] = *(uint32_t*)&p2;
            sfr[mt][j][3] = *(uint32_t*)&p3;
        }
    }

    cp_wait<0>();
    __syncthreads();

#pragma unroll
    for (int eh = 0; eh < 2; eh++) {
        float oacc[2][8][4];
#pragma unroll
        for (int i = 0; i < 2; i++)
#pragma unroll
            for (int j = 0; j < 8; j++)
#pragma unroll
                for (int r = 0; r < 4; r++) oacc[i][j][r] = 0.f;

#pragma unroll
        for (int j = 0; j < 8; j++) {
            uint32_t vfr[4][4];
#pragma unroll
            for (int ep = 0; ep < 4; ep++)
                ldm_x4_t(vfr[ep],
                         vsb + ((uint32_t)(j * 16 + lr + lm * 8) * ASTR
                                + eh * 64 + ep * 16 + lc * 8) * 2);
#pragma unroll
            for (int mt = 0; mt < 2; mt++)
#pragma unroll
                for (int nt = 0; nt < 8; nt++)
                    mma_16816(oacc[mt][nt], sfr[mt][j],
                              vfr[nt >> 1][(nt & 1) * 2], vfr[nt >> 1][(nt & 1) * 2 + 1]);
        }

#pragma unroll
        for (int ks = 0; ks < 8; ks++) {
            uint32_t afr[2][4], cfr[4][4];
            const uint32_t coff = ((uint32_t)(ks * 16 + lc * 8)) * 2;
#pragma unroll
            for (int mt = 0; mt < 2; mt++)
                ldm_x4(afr[mt], qsb + ((uint32_t)(w * 32 + mt * 16 + lr + lm * 8) * ASTR) * 2 + coff);
#pragma unroll
            for (int ep = 0; ep < 4; ep++)
                ldm_x4_t(cfr[ep],
                         esb + ((uint32_t)(ks * 16 + lr + lm * 8) * ASTR
                                + eh * 64 + ep * 16 + lc * 8) * 2);
#pragma unroll
            for (int mt = 0; mt < 2; mt++)
#pragma unroll
                for (int nt = 0; nt < 8; nt++)
                    mma_16816(oacc[mt][nt], afr[mt],
                              cfr[nt >> 1][(nt & 1) * 2], cfr[nt >> 1][(nt & 1) * 2 + 1]);
        }

#pragma unroll
        for (int mt = 0; mt < 2; mt++) {
#pragma unroll
            for (int half = 0; half < 2; half++) {
                int c = w * 32 + mt * 16 + g + half * 8;
                int s = n * CHK + c;
                unsigned short* orow = g_a2 + (size_t)(b * SEQL + s) * KP + h * HD;
#pragma unroll
                for (int nt = 0; nt < 8; nt++) {
                    int e = eh * 64 + nt * 8 + qd;
                    __half2 h2 = __floats2half2_rn(oacc[mt][nt][half * 2] * QDESCALE,
                                                   oacc[mt][nt][half * 2 + 1] * QDESCALE);
                    *(__half2*)(orow + e) = h2;
                }
            }
        }
    }
}

// ---------------------------------------------------------------------------
extern "C" void kernel_launch(void* const* d_in, const int* in_sizes, int n_in,
                              void* d_out, int out_size)
{
    const float* x  = (const float*)d_in[0];
    const float* fc = (const float*)d_in[1];
    const float* wq = (const float*)d_in[2];
    const float* wk = (const float*)d_in[3];
    const float* wv = (const float*)d_in[4];
    const float* wo = (const float*)d_in[5];
    float* out = (float*)d_out;

    cudaFuncSetAttribute(k_gemm_mma, cudaFuncAttributeMaxDynamicSharedMemorySize, GEMM_SMEM);
    cudaFuncSetAttribute(k_attn_tc, cudaFuncAttributeMaxDynamicSharedMemorySize, ATTN2_SMEM);
    cudaFuncSetAttribute(k_kvcum, cudaFuncAttributeMaxDynamicSharedMemorySize, KVC_SMEM);

    void *p_x2, *p_w2, *p_a2, *p_wo2, *p_cs;
    cudaGetSymbolAddress(&p_x2, g_x2);
    cudaGetSymbolAddress(&p_w2, g_w2);
    cudaGetSymbolAddress(&p_a2, g_a2);
    cudaGetSymbolAddress(&p_wo2, g_wo2);
    cudaGetSymbolAddress(&p_cs, g_colsum);
    unsigned short* x2  = (unsigned short*)p_x2;
    unsigned short* w2  = (unsigned short*)p_w2;
    unsigned short* a2  = (unsigned short*)p_a2;
    unsigned short* wo2 = (unsigned short*)p_wo2;

    k_cvt_all<<<10240, 256>>>(x, wq, wk, wv, wo);
    cudaMemsetAsync(p_cs, 0, BATCHN * NKV * HD * sizeof(float));

    // QKV projection (q/k/v all fp16 scatter)
    k_gemm_mma<<<dim3(32, 32), 128, GEMM_SMEM>>>(
        (const __half*)x2, (const __half*)w2, nullptr, 0);

    // RoPE-k (colsum), fused kv+prefix (also inverts colsum), rope-q
    k_rope_k<<<dim3(16, 32), 256>>>(fc);
    k_kvcum<<<64, 128, KVC_SMEM>>>();
    k_rope_q<<<8192, 256>>>(fc);

    // attention
    k_attn_tc<<<512, 128, ATTN2_SMEM>>>();

    // output projection
    k_gemm_mma<<<dim3(16, 32), 128, GEMM_SMEM>>>(
        (const __half*)a2, (const __half*)wo2, out, 1);
}

// round 14
// speedup vs baseline: 1.0223x; 1.0223x over previous
#include <cuda_runtime.h>
#include <cuda_fp16.h>
#include <cstdint>

// Problem constants
#define BATCHN 2
#define SEQL   2048
#define DIMN   2048
#define NH     16
#define NKV    8
#define HD     128
#define NCH    16
#define CHK    128
#define KP     2048
#define BKC    32
#define STR    40
#define NITG   (KP / BKC)   // 64

#define QSCALE   4096.0f
#define QDESCALE (1.0f / 4096.0f)

// ---------------------------------------------------------------------------
// Scratch
// ---------------------------------------------------------------------------
__device__ float g_kv[(size_t)BATCHN * NKV * NCH * HD * HD];
__device__ float g_colsum[BATCHN * NKV * HD];

__device__ unsigned short g_x2[(size_t)4096 * KP];
__device__ unsigned short g_w2[(size_t)4096 * KP];
__device__ unsigned short g_a2[(size_t)4096 * KP];
__device__ unsigned short g_wo2[(size_t)2048 * KP];

__device__ __half g_qh0[(size_t)BATCHN * NH * SEQL * HD];   // raw q (pre-rope) fp16
__device__ __half g_kh[(size_t)BATCHN * NKV * SEQL * HD];   // raw k (pre-rope) fp16
__device__ __half g_qh[(size_t)BATCHN * NH * SEQL * HD];    // q' * QSCALE
__device__ __half g_ekh[(size_t)BATCHN * NKV * SEQL * HD];  // exp(rope(k))
__device__ __half g_vh[(size_t)BATCHN * NKV * SEQL * HD];   // v
__device__ __half g_cumh[(size_t)BATCHN * NKV * NCH * HD * HD];

// ---------------------------------------------------------------------------
// PTX helpers
// ---------------------------------------------------------------------------
__device__ __forceinline__ uint32_t smem_u32(const void* p) {
    uint32_t a;
    asm("{ .reg .u64 t; cvta.to.shared.u64 t, %1; cvt.u32.u64 %0, t; }"
        : "=r"(a) : "l"(p));
    return a;
}
__device__ __forceinline__ void ldm_x4(uint32_t* r, uint32_t addr) {
    asm volatile("ldmatrix.sync.aligned.m8n8.x4.shared.b16 {%0,%1,%2,%3}, [%4];"
                 : "=r"(r[0]), "=r"(r[1]), "=r"(r[2]), "=r"(r[3]) : "r"(addr));
}
__device__ __forceinline__ void ldm_x4_t(uint32_t* r, uint32_t addr) {
    asm volatile("ldmatrix.sync.aligned.m8n8.x4.trans.shared.b16 {%0,%1,%2,%3}, [%4];"
                 : "=r"(r[0]), "=r"(r[1]), "=r"(r[2]), "=r"(r[3]) : "r"(addr));
}
__device__ __forceinline__ void mma_16816(float* c, const uint32_t* a,
                                          uint32_t b0, uint32_t b1) {
    asm volatile(
        "mma.sync.aligned.m16n8k16.row.col.f32.f16.f16.f32 "
        "{%0,%1,%2,%3}, {%4,%5,%6,%7}, {%8,%9}, {%0,%1,%2,%3};"
        : "+f"(c[0]), "+f"(c[1]), "+f"(c[2]), "+f"(c[3])
        : "r"(a[0]), "r"(a[1]), "r"(a[2]), "r"(a[3]), "r"(b0), "r"(b1));
}
__device__ __forceinline__ void cp16(uint32_t s, const void* g) {
    asm volatile("cp.async.cg.shared.global [%0], [%1], 16;" :: "r"(s), "l"(g));
}
__device__ __forceinline__ void cp_commit() {
    asm volatile("cp.async.commit_group;" ::: "memory");
}
template <int N> __device__ __forceinline__ void cp_wait() {
    asm volatile("cp.async.wait_group %0;" :: "n"(N) : "memory");
}

// ---------------------------------------------------------------------------
// Fused fp32 -> fp16 conversion for all inputs. Block 10239 also zeroes colsum.
// ---------------------------------------------------------------------------
__global__ __launch_bounds__(256) void k_cvt_all(
    const float* __restrict__ x,  const float* __restrict__ wq,
    const float* __restrict__ wk, const float* __restrict__ wv,
    const float* __restrict__ wo)
{
    int blk = blockIdx.x;
    if (blk == 10239 && threadIdx.x < 256) {
#pragma unroll
        for (int j = 0; j < 8; j++)
            g_colsum[threadIdx.x * 8 + j] = 0.f;
    }
    const float* src;
    unsigned short* dst;
    size_t base;
    if (blk < 4096)      { src = x;  dst = g_x2;  base = (size_t)blk * 2048; }
    else if (blk < 6144) { src = wq; dst = g_w2;  base = (size_t)(blk - 4096) * 2048; }
    else if (blk < 7168) { src = wk; dst = g_w2 + (size_t)2048 * KP; base = (size_t)(blk - 6144) * 2048; }
    else if (blk < 8192) { src = wv; dst = g_w2 + (size_t)3072 * KP; base = (size_t)(blk - 7168) * 2048; }
    else                 { src = wo; dst = g_wo2; base = (size_t)(blk - 8192) * 2048; }

    size_t i = base + (size_t)threadIdx.x * 8;
    float4 v0 = *(const float4*)(src + i);
    float4 v1 = *(const float4*)(src + i + 4);
    float f[8] = {v0.x, v0.y, v0.z, v0.w, v1.x, v1.y, v1.z, v1.w};
    __align__(16) __half o[8];
#pragma unroll
    for (int j = 0; j < 8; j++) o[j] = __float2half(f[j]);
    *(uint4*)(dst + i) = *(const uint4*)o;
}

// ---------------------------------------------------------------------------
// HMMA fp16 GEMM. 128x128 tile, 4 warps (2x2), BK=32, 3-stage, 3 CTAs/SM.
// mode 0: scatter q/k/v fp16.  mode 1: row-major fp32 C.
// ---------------------------------------------------------------------------
#define A_BUF (128 * STR)
#define B_BUF (128 * STR)
#define GEMM_SMEM ((3 * (A_BUF + B_BUF)) * 2)   // 61440 bytes

__global__ __launch_bounds__(128, 3) void k_gemm_mma(
    const __half* __restrict__ A, const __half* __restrict__ B,
    float* __restrict__ C, int mode)
{
    extern __shared__ char smraw[];
    __half* sA = (__half*)smraw;
    __half* sB = sA + 3 * A_BUF;

    const int t = threadIdx.x, lane = t & 31, wid = t >> 5;
    const int wm = wid >> 1, wn = wid & 1;
    const int m0 = blockIdx.y * 128, n0 = blockIdx.x * 128;

    uint32_t sAb = smem_u32(sA);
    uint32_t sBb = smem_u32(sB);

    const __half* ga = A + (size_t)(m0 + (t >> 2)) * KP + (t & 3) * 8;
    const __half* gb = B + (size_t)(n0 + (t >> 2)) * KP + (t & 3) * 8;
    const uint32_t so = ((uint32_t)(t >> 2) * STR + (t & 3) * 8) * 2;

    auto load_tile = [&](int buf, int i) {
        uint32_t sa = sAb + (uint32_t)buf * A_BUF * 2 + so;
        uint32_t sb = sBb + (uint32_t)buf * B_BUF * 2 + so;
        int ko = i * BKC;
#pragma unroll
        for (int j = 0; j < 4; j++)
            cp16(sa + j * 32 * STR * 2, ga + (size_t)j * 32 * KP + ko);
#pragma unroll
        for (int j = 0; j < 4; j++)
            cp16(sb + j * 32 * STR * 2, gb + (size_t)j * 32 * KP + ko);
        cp_commit();
    };

    float acc[4][8][4];
#pragma unroll
    for (int i = 0; i < 4; i++)
#pragma unroll
        for (int j = 0; j < 8; j++)
#pragma unroll
            for (int r = 0; r < 4; r++) acc[i][j][r] = 0.f;

    const int lr = lane & 7;
    const int lm = (lane >> 3) & 1;
    const int lc = lane >> 4;

    load_tile(0, 0);
    load_tile(1, 1);

    for (int i = 0; i < NITG; i++) {
        if (i == NITG - 1) cp_wait<0>(); else cp_wait<1>();
        __syncthreads();

        int buf = i % 3;
        uint32_t sa = sAb + (uint32_t)buf * A_BUF * 2;
        uint32_t sb = sBb + (uint32_t)buf * B_BUF * 2;
#pragma unroll
        for (int ks = 0; ks < 2; ks++) {
            uint32_t afr[4][4], bfr[4][4];
            const uint32_t coff = ((uint32_t)(ks * 16 + lc * 8)) * 2;
#pragma unroll
            for (int mt = 0; mt < 4; mt++)
                ldm_x4(afr[mt],
                       sa + ((uint32_t)(wm * 64 + mt * 16 + lr + lm * 8) * STR) * 2 + coff);
#pragma unroll
            for (int nt2 = 0; nt2 < 4; nt2++)
                ldm_x4(bfr[nt2],
                       sb + ((uint32_t)(wn * 64 + nt2 * 16 + lr + lm * 8) * STR) * 2 + coff);
#pragma unroll
            for (int mt = 0; mt < 4; mt++)
#pragma unroll
                for (int nt = 0; nt < 8; nt++)
                    mma_16816(acc[mt][nt], afr[mt],
                              bfr[nt >> 1][nt & 1], bfr[nt >> 1][(nt & 1) + 2]);
        }

        if (i + 2 < NITG) load_tile((i + 2) % 3, i + 2);
    }

    // epilogue
    const int g = lane >> 2, c2 = (lane & 3) * 2;
#pragma unroll
    for (int mt = 0; mt < 4; mt++) {
#pragma unroll
        for (int half = 0; half < 2; half++) {
            int m = m0 + wm * 64 + mt * 16 + g + half * 8;
            if (mode == 0) {
                int b = m >> 11, s = m & 2047;
                int ht = n0 >> 7;
                __half* dsth;
                if (ht < 16)
                    dsth = g_qh0 + (((size_t)(b * NH + ht)) * SEQL + s) * HD;
                else if (ht < 24)
                    dsth = g_kh + (((size_t)(b * NKV + (ht - 16))) * SEQL + s) * HD;
                else
                    dsth = g_vh + (((size_t)(b * NKV + (ht - 24))) * SEQL + s) * HD;
#pragma unroll
                for (int nt = 0; nt < 8; nt++) {
                    int col = wn * 64 + nt * 8 + c2;
                    __half2 h2 = __floats2half2_rn(acc[mt][nt][half * 2],
                                                   acc[mt][nt][half * 2 + 1]);
                    *(__half2*)(dsth + col) = h2;
                }
            } else {
                float* dst = C + (size_t)m * DIMN + n0;
#pragma unroll
                for (int nt = 0; nt < 8; nt++) {
                    int col = wn * 64 + nt * 8 + c2;
                    float2 v2 = make_float2(acc[mt][nt][half * 2],
                                            acc[mt][nt][half * 2 + 1]);
                    *(float2*)(dst + col) = v2;
                }
            }
        }
    }
}

// ---------------------------------------------------------------------------
// K3: ekh = exp(rope(kh)) fp16 via __expf; accumulate column sums (fp32).
// ---------------------------------------------------------------------------
__global__ __launch_bounds__(256) void k_rope_k(const float* __restrict__ fc)
{
    __shared__ float s_part[8][128];
    int bhk = blockIdx.x;
    int w   = threadIdx.x >> 5;
    int l   = threadIdx.x & 31;
    float sum0 = 0.f, sum1 = 0.f, sum2 = 0.f, sum3 = 0.f;
#pragma unroll
    for (int r = 0; r < 8; r++) {
        int s = blockIdx.y * 64 + w * 8 + r;
        size_t off = ((size_t)bhk * SEQL + s) * HD + l * 4;
        __half2 a0 = *(const __half2*)(g_kh + off);
        __half2 a1 = *(const __half2*)(g_kh + off + 2);
        float vx = __low2float(a0), vy = __high2float(a0);
        float vz = __low2float(a1), vw = __high2float(a1);
        float4 f = *(const float4*)(fc + (size_t)s * HD + l * 4);
        float o0 = vx * f.x - vy * f.y;
        float o1 = vx * f.y + vy * f.x;
        float o2 = vz * f.z - vw * f.w;
        float o3 = vz * f.w + vw * f.z;
        float e0 = __expf(o0), e1 = __expf(o1), e2 = __expf(o2), e3 = __expf(o3);
        *(__half2*)(g_ekh + off)     = __floats2half2_rn(e0, e1);
        *(__half2*)(g_ekh + off + 2) = __floats2half2_rn(e2, e3);
        sum0 += e0; sum1 += e1; sum2 += e2; sum3 += e3;
    }
    s_part[w][l * 4 + 0] = sum0;
    s_part[w][l * 4 + 1] = sum1;
    s_part[w][l * 4 + 2] = sum2;
    s_part[w][l * 4 + 3] = sum3;
    __syncthreads();
    if (threadIdx.x < 128) {
        float a = 0.f;
#pragma unroll
        for (int w2 = 0; w2 < 8; w2++) a += s_part[w2][threadIdx.x];
        atomicAdd(&g_colsum[bhk * HD + threadIdx.x], a);
    }
}

// ---------------------------------------------------------------------------
// K4: per-chunk kv = ek^T @ v on HMMA; also inverts g_colsum (fused rcp).
// ---------------------------------------------------------------------------
#define KVSTR 136
#define KV_SMEM (2 * 128 * KVSTR * 2)   // 69632 bytes

__global__ __launch_bounds__(128, 2) void k_kvchunk_tc()
{
    extern __shared__ __half smkv[];
    __half* es = smkv;
    __half* vs = smkv + 128 * KVSTR;

    if (threadIdx.x < 8) {
        int i = blockIdx.x * 8 + threadIdx.x;
        g_colsum[i] = __frcp_rn(g_colsum[i]);
    }

    const int bhk = blockIdx.x >> 4;
    const int n   = blockIdx.x & 15;
    const __half* eb = g_ekh + ((size_t)bhk * SEQL + n * CHK) * HD;
    const __half* vb = g_vh  + ((size_t)bhk * SEQL + n * CHK) * HD;
    const int t = threadIdx.x, lane = t & 31, w = t >> 5;
    uint32_t esb = smem_u32(es), vsb = smem_u32(vs);

#pragma unroll
    for (int it = 0; it < 16; it++) {
        int idx = it * 128 + t;
        int r = idx >> 4, seg = idx & 15;
        uint32_t so = ((uint32_t)r * KVSTR + seg * 8) * 2;
        cp16(esb + so, eb + (size_t)r * HD + seg * 8);
        cp16(vsb + so, vb + (size_t)r * HD + seg * 8);
    }
    cp_commit();
    cp_wait<0>();
    __syncthreads();

    const int lr = lane & 7, lm = (lane >> 3) & 1, lc = lane >> 4;
    const int g = lane >> 2, qd = (lane & 3) * 2;

    float acc[2][16][4];
#pragma unroll
    for (int i = 0; i < 2; i++)
#pragma unroll
        for (int j = 0; j < 16; j++)
#pragma unroll
            for (int r = 0; r < 4; r++) acc[i][j][r] = 0.f;

#pragma unroll
    for (int ks = 0; ks < 8; ks++) {
        uint32_t afr[2][4], tmp[4], bfr[8][4];
        const uint32_t rowb = ((uint32_t)(ks * 16 + lr + lm * 8)) * KVSTR;
#pragma unroll
        for (int mt = 0; mt < 2; mt++) {
            ldm_x4_t(tmp, esb + (rowb + w * 32 + mt * 16 + lc * 8) * 2);
            afr[mt][0] = tmp[0]; afr[mt][1] = tmp[2];
            afr[mt][2] = tmp[1]; afr[mt][3] = tmp[3];
        }
#pragma unroll
        for (int p = 0; p < 8; p++)
            ldm_x4_t(bfr[p], vsb + (rowb + p * 16 + lc * 8) * 2);
#pragma unroll
        for (int mt = 0; mt < 2; mt++)
#pragma unroll
            for (int nt = 0; nt < 16; nt++)
                mma_16816(acc[mt][nt], afr[mt],
                          bfr[nt >> 1][(nt & 1) * 2], bfr[nt >> 1][(nt & 1) * 2 + 1]);
    }

    size_t base = ((size_t)bhk * NCH + n) * (HD * HD);
#pragma unroll
    for (int mt = 0; mt < 2; mt++) {
#pragma unroll
        for (int half = 0; half < 2; half++) {
            int d = w * 32 + mt * 16 + g + half * 8;
#pragma unroll
            for (int nt = 0; nt < 16; nt++) {
                float2 v2 = make_float2(acc[mt][nt][half * 2],
                                        acc[mt][nt][half * 2 + 1]);
                *(float2*)(g_kv + base + (size_t)d * HD + nt * 8 + qd) = v2;
            }
        }
    }
}

// ---------------------------------------------------------------------------
// K2: q' = softmax(rope(qh0)*s) * invcolsum * QSCALE -> fp16 (fast math).
// ---------------------------------------------------------------------------
__global__ __launch_bounds__(256) void k_rope_q(const float* __restrict__ fc)
{
    int r = blockIdx.x * 8 + (threadIdx.x >> 5);
    int l = threadIdx.x & 31;
    int s  = r & 2047;
    int bh = r >> 11;
    int h  = bh & 15;
    int b  = bh >> 4;

    size_t off = (size_t)r * HD + l * 4;
    __half2 a0 = *(const __half2*)(g_qh0 + off);
    __half2 a1 = *(const __half2*)(g_qh0 + off + 2);
    float vx = __low2float(a0), vy = __high2float(a0);
    float vz = __low2float(a1), vw = __high2float(a1);
    float4 f = *(const float4*)(fc + (size_t)s * HD + l * 4);
    const float scale = 0.08838834764831845f;
    float o0 = (vx * f.x - vy * f.y) * scale;
    float o1 = (vx * f.y + vy * f.x) * scale;
    float o2 = (vz * f.z - vw * f.w) * scale;
    float o3 = (vz * f.w + vw * f.z) * scale;

    float mx = fmaxf(fmaxf(o0, o1), fmaxf(o2, o3));
#pragma unroll
    for (int off2 = 16; off2; off2 >>= 1) mx = fmaxf(mx, __shfl_xor_sync(0xffffffffu, mx, off2));
    float e0 = __expf(o0 - mx), e1 = __expf(o1 - mx);
    float e2 = __expf(o2 - mx), e3 = __expf(o3 - mx);
    float ss = e0 + e1 + e2 + e3;
#pragma unroll
    for (int off2 = 16; off2; off2 >>= 1) ss += __shfl_xor_sync(0xffffffffu, ss, off2);
    float inv = __fdividef(QSCALE, ss);

    const float* csp = g_colsum + ((b * NKV + (h >> 1)) * HD) + l * 4;   // 1/colsum
    float4 cs = *(const float4*)csp;
    __half* qp = g_qh + off;
    *(__half2*)(qp)     = __floats2half2_rn(e0 * inv * cs.x, e1 * inv * cs.y);
    *(__half2*)(qp + 2) = __floats2half2_rn(e2 * inv * cs.z, e3 * inv * cs.w);
}

// ---------------------------------------------------------------------------
// K5: exclusive prefix sum over chunks -> fp16 g_cumh.
// ---------------------------------------------------------------------------
__global__ void k_prefix()
{
    int bhk  = blockIdx.x;
    int elem = blockIdx.y * 256 + threadIdx.x;
    size_t base = (size_t)bhk * NCH * (HD * HD) + elem;
    float acc = 0.f;
#pragma unroll
    for (int n = 0; n < NCH; n++) {
        g_cumh[base + (size_t)n * (HD * HD)] = __float2half(acc);
        acc += g_kv[base + (size_t)n * (HD * HD)];
    }
}

// ---------------------------------------------------------------------------
// K6: per-(b,h,chunk) attention on HMMA.
// ---------------------------------------------------------------------------
#define ASTR 136
#define ATILE (128 * ASTR)
#define ATTN2_SMEM (3 * ATILE * 2)   // 104448 bytes

__global__ __launch_bounds__(128, 2) void k_attn_tc()
{
    extern __shared__ __half smh[];
    __half* qs = smh;
    __half* es = smh + ATILE;
    __half* vs = smh + 2 * ATILE;

    const int bid = blockIdx.x;
    const int b = bid >> 8;
    const int h = (bid >> 4) & 15;
    const int n = bid & 15;
    const int hk = h >> 1;
    const int t = threadIdx.x, lane = t & 31, w = t >> 5;

    const __half* qb = g_qh  + (((size_t)(b * NH  + h ) * SEQL) + n * CHK) * HD;
    const __half* eb = g_ekh + (((size_t)(b * NKV + hk) * SEQL) + n * CHK) * HD;
    const __half* vb = g_vh  + (((size_t)(b * NKV + hk) * SEQL) + n * CHK) * HD;
    const __half* cb = g_cumh + ((size_t)(b * NKV + hk) * NCH + n) * (HD * HD);

    uint32_t qsb = smem_u32(qs), esb = smem_u32(es), vsb = smem_u32(vs);

#pragma unroll
    for (int it = 0; it < 16; it++) {
        int idx = it * 128 + t;
        int r = idx >> 4, seg = idx & 15;
        uint32_t so = ((uint32_t)r * ASTR + seg * 8) * 2;
        cp16(qsb + so, qb + (size_t)r * HD + seg * 8);
        cp16(esb + so, eb + (size_t)r * HD + seg * 8);
        cp16(vsb + so, vb + (size_t)r * HD + seg * 8);
    }
    cp_commit();
    cp_wait<0>();
    __syncthreads();

    const int lr = lane & 7, lm = (lane >> 3) & 1, lc = lane >> 4;
    const int g = lane >> 2, qd = (lane & 3) * 2;

    float sacc[2][16][4];
#pragma unroll
    for (int i = 0; i < 2; i++)
#pragma unroll
        for (int j = 0; j < 16; j++)
#pragma unroll
            for (int r = 0; r < 4; r++) sacc[i][j][r] = 0.f;

#pragma unroll
    for (int ks = 0; ks < 8; ks++) {
        uint32_t afr[2][4], bfr[8][4];
        const uint32_t coff = ((uint32_t)(ks * 16 + lc * 8)) * 2;
#pragma unroll
        for (int mt = 0; mt < 2; mt++)
            ldm_x4(afr[mt], qsb + ((uint32_t)(w * 32 + mt * 16 + lr + lm * 8) * ASTR) * 2 + coff);
#pragma unroll
        for (int p = 0; p < 8; p++)
            ldm_x4(bfr[p], esb + ((uint32_t)(p * 16 + lr + lm * 8) * ASTR) * 2 + coff);
#pragma unroll
        for (int mt = 0; mt < 2; mt++)
#pragma unroll
            for (int nt = 0; nt < 16; nt++)
                mma_16816(sacc[mt][nt], afr[mt],
                          bfr[nt >> 1][nt & 1], bfr[nt >> 1][(nt & 1) + 2]);
    }

    __syncthreads();
#pragma unroll
    for (int it = 0; it < 16; it++) {
        int idx = it * 128 + t;
        int r = idx >> 4, seg = idx & 15;
        cp16(esb + ((uint32_t)r * ASTR + seg * 8) * 2, cb + (size_t)r * HD + seg * 8);
    }
    cp_commit();

    uint32_t sfr[2][8][4];
#pragma unroll
    for (int mt = 0; mt < 2; mt++) {
        int c0 = w * 32 + mt * 16 + g;
#pragma unroll
        for (int j = 0; j < 8; j++) {
            int mA = j * 16 + qd;
            int mB = j * 16 + 8 + qd;
            float* e0 = sacc[mt][2 * j];
            float* e1 = sacc[mt][2 * j + 1];
            __half2 p0 = __floats2half2_rn(mA     <= c0     ? e0[0] : 0.f,
                                           mA + 1 <= c0     ? e0[1] : 0.f);
            __half2 p1 = __floats2half2_rn(mA     <= c0 + 8 ? e0[2] : 0.f,
                                           mA + 1 <= c0 + 8 ? e0[3] : 0.f);
            __half2 p2 = __floats2half2_rn(mB     <= c0     ? e1[0] : 0.f,
                                           mB + 1 <= c0     ? e1[1] : 0.f);
            __half2 p3 = __floats2half2_rn(mB     <= c0 + 8 ? e1[2] : 0.f,
                                           mB + 1 <= c0 + 8 ? e1[3] : 0.f);
            sfr[mt][j][0] = *(uint32_t*)&p0;
            sfr[mt][j][1] = *(uint32_t*)&p1;
            sfr[mt][j][2] = *(uint32_t*)&p2;
            sfr[mt][j][3] = *(uint32_t*)&p3;
        }
    }

    cp_wait<0>();
    __syncthreads();

#pragma unroll
    for (int eh = 0; eh < 2; eh++) {
        float oacc[2][8][4];
#pragma unroll
        for (int i = 0; i < 2; i++)
#pragma unroll
            for (int j = 0; j < 8; j++)
#pragma unroll
                for (int r = 0; r < 4; r++) oacc[i][j][r] = 0.f;

#pragma unroll
        for (int j = 0; j < 8; j++) {
            uint32_t vfr[4][4];
#pragma unroll
            for (int ep = 0; ep < 4; ep++)
                ldm_x4_t(vfr[ep],
                         vsb + ((uint32_t)(j * 16 + lr + lm * 8) * ASTR
                                + eh * 64 + ep * 16 + lc * 8) * 2);
#pragma unroll
            for (int mt = 0; mt < 2; mt++)
#pragma unroll
                for (int nt = 0; nt < 8; nt++)
                    mma_16816(oacc[mt][nt], sfr[mt][j],
                              vfr[nt >> 1][(nt & 1) * 2], vfr[nt >> 1][(nt & 1) * 2 + 1]);
        }

#pragma unroll
        for (int ks = 0; ks < 8; ks++) {
            uint32_t afr[2][4], cfr[4][4];
            const uint32_t coff = ((uint32_t)(ks * 16 + lc * 8)) * 2;
#pragma unroll
            for (int mt = 0; mt < 2; mt++)
                ldm_x4(afr[mt], qsb + ((uint32_t)(w * 32 + mt * 16 + lr + lm * 8) * ASTR) * 2 + coff);
#pragma unroll
            for (int ep = 0; ep < 4; ep++)
                ldm_x4_t(cfr[ep],
                         esb + ((uint32_t)(ks * 16 + lr + lm * 8) * ASTR
                                + eh * 64 + ep * 16 + lc * 8) * 2);
#pragma unroll
            for (int mt = 0; mt < 2; mt++)
#pragma unroll
                for (int nt = 0; nt < 8; nt++)
                    mma_16816(oacc[mt][nt], afr[mt],
                              cfr[nt >> 1][(nt & 1) * 2], cfr[nt >> 1][(nt & 1) * 2 + 1]);
        }

#pragma unroll
        for (int mt = 0; mt < 2; mt++) {
#pragma unroll
            for (int half = 0; half < 2; half++) {
                int c = w * 32 + mt * 16 + g + half * 8;
                int s = n * CHK + c;
                unsigned short* orow = g_a2 + (size_t)(b * SEQL + s) * KP + h * HD;
#pragma unroll
                for (int nt = 0; nt < 8; nt++) {
                    int e = eh * 64 + nt * 8 + qd;
                    __half2 h2 = __floats2half2_rn(oacc[mt][nt][half * 2] * QDESCALE,
                                                   oacc[mt][nt][half * 2 + 1] * QDESCALE);
                    *(__half2*)(orow + e) = h2;
                }
            }
        }
    }
}

// ---------------------------------------------------------------------------
extern "C" void kernel_launch(void* const* d_in, const int* in_sizes, int n_in,
                              void* d_out, int out_size)
{
    const float* x  = (const float*)d_in[0];
    const float* fc = (const float*)d_in[1];
    const float* wq = (const float*)d_in[2];
    const float* wk = (const float*)d_in[3];
    const float* wv = (const float*)d_in[4];
    const float* wo = (const float*)d_in[5];
    float* out = (float*)d_out;

    cudaFuncSetAttribute(k_gemm_mma, cudaFuncAttributeMaxDynamicSharedMemorySize, GEMM_SMEM);
    cudaFuncSetAttribute(k_attn_tc, cudaFuncAttributeMaxDynamicSharedMemorySize, ATTN2_SMEM);
    cudaFuncSetAttribute(k_kvchunk_tc, cudaFuncAttributeMaxDynamicSharedMemorySize, KV_SMEM);

    void *p_x2, *p_w2, *p_a2, *p_wo2;
    cudaGetSymbolAddress(&p_x2, g_x2);
    cudaGetSymbolAddress(&p_w2, g_w2);
    cudaGetSymbolAddress(&p_a2, g_a2);
    cudaGetSymbolAddress(&p_wo2, g_wo2);
    unsigned short* x2  = (unsigned short*)p_x2;
    unsigned short* w2  = (unsigned short*)p_w2;
    unsigned short* a2  = (unsigned short*)p_a2;
    unsigned short* wo2 = (unsigned short*)p_wo2;

    // conversions + colsum zeroing in one kernel
    k_cvt_all<<<10240, 256>>>(x, wq, wk, wv, wo);

    // QKV projection (q/k/v all fp16 scatter)
    k_gemm_mma<<<dim3(32, 32), 128, GEMM_SMEM>>>(
        (const __half*)x2, (const __half*)w2, nullptr, 0);

    // RoPE-k (colsum), kvchunk (also inverts colsum), rope-q
    k_rope_k<<<dim3(16, 32), 256>>>(fc);
    k_kvchunk_tc<<<256, 128, KV_SMEM>>>();
    k_rope_q<<<8192, 256>>>(fc);

    // prefix + attention
    k_prefix<<<dim3(16, 64), 256>>>();
    k_attn_tc<<<512, 128, ATTN2_SMEM>>>();

    // output projection
    k_gemm_mma<<<dim3(16, 32), 128, GEMM_SMEM>>>(
        (const __half*)a2, (const __half*)wo2, out, 1);
}